// round 3
// baseline (speedup 1.0000x reference)
#include <cuda_runtime.h>
#include <cuda_bf16.h>
#include <math.h>

// WaveNet — bf16x3 split tensor-core version (mma.sync.m16n8k16, fp32 accum).
// Each fp32 operand x is split hi=bf16(x), lo=bf16(x-hi); product computed as
// hi*hi + hi*lo + lo*hi (3 mmas), error ~2^-18. hi/lo packed in one 32-bit
// smem word per element; smem laid out in "fragment order" so each thread's
// mma fragment is one contiguous LDS.128.

#define HS 65536            // h row stride (time)
#define TT 128              // time tile
#define TOUT 63489          // T - 2048 + 1
#define NLAYER 20

__device__ float g_h[2][64 * HS];     // 2 x 16 MB (L2-resident ping-pong)
__device__ float g_skip[64 * TOUT];   // 16.2 MB

// ---------------------------------------------------------------------------
__device__ __forceinline__ unsigned pack_hl(float x) {
    __nv_bfloat16 h = __float2bfloat16(x);
    float hf = __bfloat162float(h);
    __nv_bfloat16 l = __float2bfloat16(x - hf);
    return (unsigned)__bfloat16_as_ushort(h) |
           ((unsigned)__bfloat16_as_ushort(l) << 16);
}

// A operand (M x K), fragment order for m16n8k16: tile (m/16, k/16) is 256
// contiguous words; within tile, lane's 8 words are contiguous.
__device__ __forceinline__ int addrA(int m, int k, int kt16) {
    int lane = ((m & 7) << 2) | ((k >> 1) & 3);
    int w = (k & 1) | (((m >> 3) & 1) << 1) | (((k >> 3) & 1) << 2);
    return ((((m >> 4) * kt16 + (k >> 4)) << 8) + (lane << 3) + w);
}
// B operand (K x N=TT): tile (k/16, t/8) is 128 contiguous words; lane's 4
// words contiguous.
__device__ __forceinline__ int addrB(int k, int t) {
    int lane = ((t & 7) << 2) | ((k >> 1) & 3);
    int w = (k & 1) | (((k >> 3) & 1) << 1);
    return ((((k >> 4) * (TT >> 3) + (t >> 3)) << 7) + (lane << 2) + w);
}

__device__ __forceinline__ void mma_bf(float* d, const unsigned* a, const unsigned* b) {
    asm volatile(
        "mma.sync.aligned.m16n8k16.row.col.f32.bf16.bf16.f32 "
        "{%0,%1,%2,%3},{%4,%5,%6,%7},{%8,%9},{%0,%1,%2,%3};\n"
        : "+f"(d[0]), "+f"(d[1]), "+f"(d[2]), "+f"(d[3])
        : "r"(a[0]), "r"(a[1]), "r"(a[2]), "r"(a[3]), "r"(b[0]), "r"(b[1]));
}

__device__ __forceinline__ void loadA(const unsigned* s, int mtile, int kc,
                                      int kt16, int lane,
                                      unsigned* Ah, unsigned* Al) {
    const uint4* p = (const uint4*)(s + (((mtile * kt16 + kc) << 8) + (lane << 3)));
    uint4 q0 = p[0], q1 = p[1];
    Ah[0] = __byte_perm(q0.x, q0.y, 0x5410); Al[0] = __byte_perm(q0.x, q0.y, 0x7632);
    Ah[1] = __byte_perm(q0.z, q0.w, 0x5410); Al[1] = __byte_perm(q0.z, q0.w, 0x7632);
    Ah[2] = __byte_perm(q1.x, q1.y, 0x5410); Al[2] = __byte_perm(q1.x, q1.y, 0x7632);
    Ah[3] = __byte_perm(q1.z, q1.w, 0x5410); Al[3] = __byte_perm(q1.z, q1.w, 0x7632);
}
__device__ __forceinline__ void loadB(const unsigned* s, int kc, int ntile,
                                      int lane, unsigned* Bh, unsigned* Bl) {
    const uint4* p = (const uint4*)(s + (((kc * (TT >> 3) + ntile) << 7) + (lane << 2)));
    uint4 q = *p;
    Bh[0] = __byte_perm(q.x, q.y, 0x5410); Bl[0] = __byte_perm(q.x, q.y, 0x7632);
    Bh[1] = __byte_perm(q.z, q.w, 0x5410); Bl[1] = __byte_perm(q.z, q.w, 0x7632);
}

__device__ __forceinline__ float fast_tanh(float x) {
    float e = __expf(-2.0f * fabsf(x));
    float r = __fdividef(1.0f - e, 1.0f + e);
    return copysignf(r, x);
}
__device__ __forceinline__ float fast_sig(float x) {
    return __fdividef(1.0f, 1.0f + __expf(-x));
}

// ---------------------------------------------------------------------------
__global__ void init_kernel(const float* __restrict__ input,
                            const float* __restrict__ w0,
                            const float* __restrict__ b0) {
    int stride = gridDim.x * blockDim.x;
    for (int idx = blockIdx.x * blockDim.x + threadIdx.x; idx < 64 * HS; idx += stride) {
        int c = idx >> 16;
        int t = idx & (HS - 1);
        g_h[0][idx] = w0[c] * input[t] + b0[c];
    }
    for (int idx = blockIdx.x * blockDim.x + threadIdx.x; idx < 64 * TOUT; idx += stride) {
        g_skip[idx] = 0.0f;
    }
}

// ---------------------------------------------------------------------------
// One dilated layer (tensor-core).
// smem (words): sW1[16384] | sW2[8192] | sX[16384] (reused as fp32 sF) | sZ[8192]
__global__ void __launch_bounds__(512, 1) layer_kernel(
    const float* __restrict__ wf, const float* __restrict__ wg,
    const float* __restrict__ wr, const float* __restrict__ ws,
    const float* __restrict__ bf, const float* __restrict__ bg,
    const float* __restrict__ br, const float* __restrict__ bs,
    int inbuf, int W, int d, int skip_shift)
{
    extern __shared__ unsigned smem[];
    unsigned* sW1 = smem;                // 128x128 A-frag packed
    unsigned* sW2 = smem + 16384;        // 128x64  A-frag packed
    unsigned* sX  = smem + 24576;        // 128xTT  B-frag packed
    unsigned* sZ  = smem + 40960;        // 64xTT   B-frag packed
    float* sF = (float*)sX;              // fp32 activations (reuse)

    const float* __restrict__ hin = g_h[inbuf];
    float* __restrict__ hout = g_h[1 - inbuf];
    const int tid = threadIdx.x;
    const int lane = tid & 31;
    const int wrp = tid >> 5;
    const int wm = wrp >> 2, wn = wrp & 3;
    const int m0 = wm * 32, n0 = wn * 32;

    // Stage weights in fragment order (once per CTA).
    for (int idx = tid; idx < 128 * 128; idx += 512) {
        int k = idx >> 7, m = idx & 127;
        int c = k & 63, lr = k >> 6;
        float v = (m < 64) ? wf[(m * 64 + c) * 2 + lr]
                           : wg[((m - 64) * 64 + c) * 2 + lr];
        sW1[addrA(m, k, 8)] = pack_hl(v);
    }
    for (int idx = tid; idx < 128 * 64; idx += 512) {
        int k = idx >> 7, m = idx & 127;   // k in [0,64)
        float v = (m < 64) ? wr[m * 64 + k] : ws[(m - 64) * 64 + k];
        sW2[addrA(m, k, 4)] = pack_hl(v);
    }
    __syncthreads();

    const int Wout = W - d;
    const int ntiles = (Wout + TT - 1) / TT;

    for (int tile = blockIdx.x; tile < ntiles; tile += gridDim.x) {
        const int t0 = tile * TT;

        // Stage X = [left; right] packed in B-frag order.
        for (int idx = tid; idx < 128 * TT; idx += 512) {
            int k = idx >> 7, t = idx & (TT - 1);
            int c = k & 63;
            int lt = t0 + t;
            float v = 0.0f;
            if (lt < Wout) v = hin[c * HS + lt + ((k >= 64) ? d : 0)];
            sX[addrB(k, t)] = pack_hl(v);
        }
        __syncthreads();

        // GEMM1: 128 x TT, K=128 (8 chunks of 16)
        float acc[2][4][4];
        #pragma unroll
        for (int a = 0; a < 2; a++)
            #pragma unroll
            for (int b = 0; b < 4; b++)
                #pragma unroll
                for (int r = 0; r < 4; r++) acc[a][b][r] = 0.0f;

        #pragma unroll
        for (int kc = 0; kc < 8; kc++) {
            unsigned Ah[2][4], Al[2][4], Bh[4][2], Bl[4][2];
            loadA(sW1, (m0 >> 4),     kc, 8, lane, Ah[0], Al[0]);
            loadA(sW1, (m0 >> 4) + 1, kc, 8, lane, Ah[1], Al[1]);
            #pragma unroll
            for (int nt = 0; nt < 4; nt++)
                loadB(sX, kc, (n0 >> 3) + nt, lane, Bh[nt], Bl[nt]);
            #pragma unroll
            for (int mt = 0; mt < 2; mt++)
                #pragma unroll
                for (int nt = 0; nt < 4; nt++) {
                    mma_bf(acc[mt][nt], Ah[mt], Bh[nt]);
                    mma_bf(acc[mt][nt], Ah[mt], Bl[nt]);
                    mma_bf(acc[mt][nt], Al[mt], Bh[nt]);
                }
        }
        __syncthreads();   // all sX reads done

        // Activations -> sF (fp32, reuses sX region)
        #pragma unroll
        for (int mt = 0; mt < 2; mt++) {
            int mbase = m0 + mt * 16 + (lane >> 2);
            #pragma unroll
            for (int nt = 0; nt < 4; nt++) {
                int tb = n0 + nt * 8 + ((lane & 3) << 1);
                #pragma unroll
                for (int r = 0; r < 4; r++) {
                    int m = mbase + ((r & 2) ? 8 : 0);
                    int t = tb + (r & 1);
                    float v = acc[mt][nt][r];
                    v = (m < 64) ? fast_tanh(v + bf[m])
                                 : fast_sig(v + bg[m - 64]);
                    sF[m * TT + t] = v;
                }
            }
        }
        __syncthreads();

        // z = tanh(f)*sig(g), packed into sZ (B-frag order)
        for (int idx = tid; idx < 64 * TT; idx += 512) {
            int c = idx >> 7, t = idx & (TT - 1);
            float z = sF[c * TT + t] * sF[(c + 64) * TT + t];
            sZ[addrB(c, t)] = pack_hl(z);
        }
        __syncthreads();

        // GEMM2: 128 x TT, K=64 (4 chunks)
        float acc2[2][4][4];
        #pragma unroll
        for (int a = 0; a < 2; a++)
            #pragma unroll
            for (int b = 0; b < 4; b++)
                #pragma unroll
                for (int r = 0; r < 4; r++) acc2[a][b][r] = 0.0f;

        #pragma unroll
        for (int kc = 0; kc < 4; kc++) {
            unsigned Ah[2][4], Al[2][4], Bh[4][2], Bl[4][2];
            loadA(sW2, (m0 >> 4),     kc, 4, lane, Ah[0], Al[0]);
            loadA(sW2, (m0 >> 4) + 1, kc, 4, lane, Ah[1], Al[1]);
            #pragma unroll
            for (int nt = 0; nt < 4; nt++)
                loadB(sZ, kc, (n0 >> 3) + nt, lane, Bh[nt], Bl[nt]);
            #pragma unroll
            for (int mt = 0; mt < 2; mt++)
                #pragma unroll
                for (int nt = 0; nt < 4; nt++) {
                    mma_bf(acc2[mt][nt], Ah[mt], Bh[nt]);
                    mma_bf(acc2[mt][nt], Ah[mt], Bl[nt]);
                    mma_bf(acc2[mt][nt], Al[mt], Bh[nt]);
                }
        }

        // Epilogue
        #pragma unroll
        for (int mt = 0; mt < 2; mt++) {
            int mbase = m0 + mt * 16 + (lane >> 2);
            #pragma unroll
            for (int nt = 0; nt < 4; nt++) {
                int tb = n0 + nt * 8 + ((lane & 3) << 1);
                #pragma unroll
                for (int r = 0; r < 4; r++) {
                    int m = mbase + ((r & 2) ? 8 : 0);
                    int gt = t0 + tb + (r & 1);
                    float v = acc2[mt][nt][r];
                    if (m < 64) {
                        if (gt < Wout)
                            hout[m * HS + gt] = v + br[m] + hin[m * HS + gt + d];
                    } else {
                        int gc = gt - skip_shift;
                        if (gt < Wout && gc >= 0 && gc < TOUT)
                            g_skip[(m - 64) * TOUT + gc] += v + bs[m - 64];
                    }
                }
            }
        }
        __syncthreads();
    }
}

// ---------------------------------------------------------------------------
// Output head, same bf16x3 machinery.
// smem (words): sW0[4096] | sW1o[16384] | sB0[8192] | sB1[8192]
__global__ void __launch_bounds__(512, 1) final_kernel(
    const float* __restrict__ alpha,
    const float* __restrict__ w_out0, const float* __restrict__ b_out0,
    const float* __restrict__ w_out1, const float* __restrict__ b_out1,
    float* __restrict__ out)
{
    extern __shared__ unsigned smem[];
    unsigned* sW0  = smem;            // 64x64   A-frag
    unsigned* sW1o = smem + 4096;     // 256x64  A-frag
    unsigned* sB0  = smem + 20480;    // 64xTT   B-frag (skip act)
    unsigned* sB1  = smem + 28672;    // 64xTT   B-frag (mid act)

    const int tid = threadIdx.x, lane = tid & 31, wrp = tid >> 5;
    const int wm = wrp >> 2, wn = wrp & 3;
    const int n0 = wn * 32;

    for (int idx = tid; idx < 64 * 64; idx += 512) {
        int m = idx >> 6, k = idx & 63;
        sW0[addrA(m, k, 4)] = pack_hl(w_out0[m * 64 + k]);
    }
    for (int idx = tid; idx < 256 * 64; idx += 512) {
        int m = idx >> 6, k = idx & 63;
        sW1o[addrA(m, k, 4)] = pack_hl(w_out1[m * 64 + k]);
    }
    __syncthreads();

    const int ntiles = (TOUT + TT - 1) / TT;
    for (int tile = blockIdx.x; tile < ntiles; tile += gridDim.x) {
        const int t0 = tile * TT;

        // Stage skip tile with leaky-relu(alpha0), packed B-frag.
        for (int idx = tid; idx < 64 * TT; idx += 512) {
            int c = idx >> 7, t = idx & (TT - 1);
            int gt = t0 + t;
            float v = (gt < TOUT) ? g_skip[c * TOUT + gt] : 0.0f;
            v = (v > 0.0f) ? v : alpha[c] * v;
            sB0[addrB(c, t)] = pack_hl(v);
        }
        __syncthreads();

        // GEMM0: 64 x TT, K=64. warp tile 16x32 (mtile = wm).
        float acc0[4][4];
        #pragma unroll
        for (int b = 0; b < 4; b++)
            #pragma unroll
            for (int r = 0; r < 4; r++) acc0[b][r] = 0.0f;

        #pragma unroll
        for (int kc = 0; kc < 4; kc++) {
            unsigned Ah[4], Al[4], Bh[4][2], Bl[4][2];
            loadA(sW0, wm, kc, 4, lane, Ah, Al);
            #pragma unroll
            for (int nt = 0; nt < 4; nt++)
                loadB(sB0, kc, (n0 >> 3) + nt, lane, Bh[nt], Bl[nt]);
            #pragma unroll
            for (int nt = 0; nt < 4; nt++) {
                mma_bf(acc0[nt], Ah, Bh[nt]);
                mma_bf(acc0[nt], Ah, Bl[nt]);
                mma_bf(acc0[nt], Al, Bh[nt]);
            }
        }
        // bias + lrelu(alpha1), pack directly into sB1 (disjoint from sB0)
        #pragma unroll
        for (int nt = 0; nt < 4; nt++) {
            int tb = n0 + nt * 8 + ((lane & 3) << 1);
            #pragma unroll
            for (int r = 0; r < 4; r++) {
                int m = wm * 16 + (lane >> 2) + ((r & 2) ? 8 : 0);
                int t = tb + (r & 1);
                float v = acc0[nt][r] + b_out0[m];
                v = (v > 0.0f) ? v : alpha[64 + m] * v;
                sB1[addrB(m, t)] = pack_hl(v);
            }
        }
        __syncthreads();

        // GEMM1: 256 x TT, K=64. warp tile 64x32 (mtiles wm*4..wm*4+3).
        float acc1[4][4][4];
        #pragma unroll
        for (int a = 0; a < 4; a++)
            #pragma unroll
            for (int b = 0; b < 4; b++)
                #pragma unroll
                for (int r = 0; r < 4; r++) acc1[a][b][r] = 0.0f;

        #pragma unroll
        for (int kc = 0; kc < 4; kc++) {
            unsigned Ah[4][4], Al[4][4], Bh[4][2], Bl[4][2];
            #pragma unroll
            for (int mt = 0; mt < 4; mt++)
                loadA(sW1o, wm * 4 + mt, kc, 4, lane, Ah[mt], Al[mt]);
            #pragma unroll
            for (int nt = 0; nt < 4; nt++)
                loadB(sB1, kc, (n0 >> 3) + nt, lane, Bh[nt], Bl[nt]);
            #pragma unroll
            for (int mt = 0; mt < 4; mt++)
                #pragma unroll
                for (int nt = 0; nt < 4; nt++) {
                    mma_bf(acc1[mt][nt], Ah[mt], Bh[nt]);
                    mma_bf(acc1[mt][nt], Ah[mt], Bl[nt]);
                    mma_bf(acc1[mt][nt], Al[mt], Bh[nt]);
                }
        }
        #pragma unroll
        for (int mt = 0; mt < 4; mt++) {
            int mbase = wm * 64 + mt * 16 + (lane >> 2);
            #pragma unroll
            for (int nt = 0; nt < 4; nt++) {
                int tb = n0 + nt * 8 + ((lane & 3) << 1);
                #pragma unroll
                for (int r = 0; r < 4; r++) {
                    int m = mbase + ((r & 2) ? 8 : 0);
                    int gt = t0 + tb + (r & 1);
                    if (gt < TOUT)
                        out[m * TOUT + gt] = acc1[mt][nt][r] + b_out1[m];
                }
            }
        }
        __syncthreads();
    }
}

// ---------------------------------------------------------------------------
extern "C" void kernel_launch(void* const* d_in, const int* in_sizes, int n_in,
                              void* d_out, int out_size) {
    const float* input  = (const float*)d_in[0];
    const float* w0     = (const float*)d_in[1];
    const float* b0     = (const float*)d_in[2];
    const float* wf     = (const float*)d_in[3];
    const float* bf     = (const float*)d_in[4];
    const float* wg     = (const float*)d_in[5];
    const float* bg     = (const float*)d_in[6];
    const float* wr     = (const float*)d_in[7];
    const float* br     = (const float*)d_in[8];
    const float* ws     = (const float*)d_in[9];
    const float* bs     = (const float*)d_in[10];
    const float* alpha  = (const float*)d_in[11];
    const float* w_out0 = (const float*)d_in[12];
    const float* b_out0 = (const float*)d_in[13];
    const float* w_out1 = (const float*)d_in[14];
    const float* b_out1 = (const float*)d_in[15];

    const int SMEM_LAYER = 49152 * 4;   // 192 KB
    const int SMEM_FINAL = 36864 * 4;   // 144 KB
    cudaFuncSetAttribute(layer_kernel, cudaFuncAttributeMaxDynamicSharedMemorySize, SMEM_LAYER);
    cudaFuncSetAttribute(final_kernel, cudaFuncAttributeMaxDynamicSharedMemorySize, SMEM_FINAL);

    init_kernel<<<512, 256>>>(input, w0, b0);

    int W = HS;
    int offset = 2048;
    int buf = 0;
    for (int i = 0; i < NLAYER; i++) {
        int d = 1 << (i % 10);
        offset -= d;
        layer_kernel<<<148, 512, SMEM_LAYER>>>(
            wf + i * 64 * 64 * 2, wg + i * 64 * 64 * 2,
            wr + i * 64 * 64,     ws + i * 64 * 64,
            bf + i * 64, bg + i * 64, br + i * 64, bs + i * 64,
            buf, W, d, offset - 1);
        W -= d;
        buf ^= 1;
    }

    final_kernel<<<148, 512, SMEM_FINAL>>>(alpha, w_out0, b_out0, w_out1, b_out1,
                                           (float*)d_out);
}

// round 4
// speedup vs baseline: 1.1629x; 1.1629x over previous
#include <cuda_runtime.h>
#include <cuda_bf16.h>
#include <math.h>

#define HS 65536
#define TOUT 63489
#define NLAYER 20
#define FTT 128

__device__ __nv_bfloat16 g_hh[2*64*HS + 8192];
__device__ __nv_bfloat16 g_hl[2*64*HS + 8192];
__device__ float g_skip[64*TOUT];

__device__ __forceinline__ unsigned bf2pack(__nv_bfloat16 a, __nv_bfloat16 b){
    return (unsigned)__bfloat16_as_ushort(a) | ((unsigned)__bfloat16_as_ushort(b)<<16);
}
__device__ __forceinline__ void split2(float a, float b, unsigned& h, unsigned& l){
    __nv_bfloat16 ha=__float2bfloat16(a), hb=__float2bfloat16(b);
    h = bf2pack(ha,hb);
    l = bf2pack(__float2bfloat16(a-__bfloat162float(ha)), __float2bfloat16(b-__bfloat162float(hb)));
}
__device__ __forceinline__ float blo(unsigned u){ return __bfloat162float(__ushort_as_bfloat16((unsigned short)(u&0xffff))); }
__device__ __forceinline__ float bhi(unsigned u){ return __bfloat162float(__ushort_as_bfloat16((unsigned short)(u>>16))); }
__device__ __forceinline__ void ldsm4t(unsigned a, unsigned* d){
    asm volatile("ldmatrix.sync.aligned.m8n8.x4.trans.shared.b16 {%0,%1,%2,%3},[%4];"
        :"=r"(d[0]),"=r"(d[1]),"=r"(d[2]),"=r"(d[3]):"r"(a));
}
__device__ __forceinline__ void mma_bf(float* d, const unsigned* a, const unsigned* b){
    asm volatile("mma.sync.aligned.m16n8k16.row.col.f32.bf16.bf16.f32 "
        "{%0,%1,%2,%3},{%4,%5,%6,%7},{%8,%9},{%0,%1,%2,%3};\n"
        :"+f"(d[0]),"+f"(d[1]),"+f"(d[2]),"+f"(d[3])
        :"r"(a[0]),"r"(a[1]),"r"(a[2]),"r"(a[3]),"r"(b[0]),"r"(b[1]));
}
__device__ __forceinline__ float fast_tanh(float x){
    float e=__expf(-2.0f*fabsf(x)); return copysignf(__fdividef(1.0f-e,1.0f+e),x);
}
__device__ __forceinline__ float fast_sig(float x){ return __fdividef(1.0f,1.0f+__expf(-x)); }

__global__ void init_kernel(const float* __restrict__ in, const float* __restrict__ w0,
                            const float* __restrict__ b0){
    int st = gridDim.x*blockDim.x;
    for (int i = blockIdx.x*blockDim.x+threadIdx.x; i < 64*HS; i += st){
        float v = w0[i>>16]*in[i&(HS-1)] + b0[i>>16];
        __nv_bfloat16 h = __float2bfloat16(v);
        g_hh[i] = h; g_hl[i] = __float2bfloat16(v-__bfloat162float(h));
    }
    for (int i = blockIdx.x*blockDim.x+threadIdx.x; i < 64*TOUT; i += st) g_skip[i] = 0.0f;
}

// smem bytes: Xhi[0,64K) Xlo[64K,128K) W1hi[128K,160K) W1lo[160K,192K) W2hi[192K,208K) W2lo[208K,224K)
__global__ void __launch_bounds__(512,1) layer_kernel(
    const float* __restrict__ wf, const float* __restrict__ wg,
    const float* __restrict__ wr, const float* __restrict__ ws,
    const float* __restrict__ bfp, const float* __restrict__ bgp,
    const float* __restrict__ brp, const float* __restrict__ bsp,
    int inbuf, int W, int d, int skip_shift)
{
    extern __shared__ unsigned char smem[];
    unsigned char* sXh = smem;
    unsigned char* sXl = smem + 65536;
    unsigned* sW1h = (unsigned*)(smem+131072);
    unsigned* sW1l = (unsigned*)(smem+163840);
    unsigned* sW2h = (unsigned*)(smem+196608);
    unsigned* sW2l = (unsigned*)(smem+212992);
    const int tid=threadIdx.x, lane=tid&31, warp=tid>>5;
    const int tw = warp*16, tw3 = warp*2;

    const __nv_bfloat16* hinh = g_hh + (size_t)inbuf*(64*HS);
    const __nv_bfloat16* hinl = g_hl + (size_t)inbuf*(64*HS);
    __nv_bfloat16* houth = g_hh + (size_t)(1-inbuf)*(64*HS);
    __nv_bfloat16* houtl = g_hl + (size_t)(1-inbuf)*(64*HS);

    // stage weights in mma A-fragment order
    for (int idx=tid; idx<128*64; idx+=512){
        int m=idx&127, k0=(idx>>7)*2;
        int c0=k0&63, l0=k0>>6, c1=(k0+1)&63, l1=(k0+1)>>6;
        float v0 = (m<64)? wf[(m*64+c0)*2+l0] : wg[((m-64)*64+c0)*2+l0];
        float v1 = (m<64)? wf[(m*64+c1)*2+l1] : wg[((m-64)*64+c1)*2+l1];
        int ml=m&15, kl=k0&15;
        int r = ((ml>>3)&1) | (((kl>>3)&1)<<1);
        int w = (((m>>4)*8 + (k0>>4))<<7) + ((ml&7)*4 + ((kl>>1)&3))*4 + r;
        unsigned h,l; split2(v0,v1,h,l); sW1h[w]=h; sW1l[w]=l;
    }
    for (int idx=tid; idx<128*32; idx+=512){
        int m=idx&127, k0=(idx>>7)*2;
        float v0 = (m<64)? wr[m*64+k0]   : ws[(m-64)*64+k0];
        float v1 = (m<64)? wr[m*64+k0+1] : ws[(m-64)*64+k0+1];
        int ml=m&15, kl=k0&15;
        int r = ((ml>>3)&1) | (((kl>>3)&1)<<1);
        int w = (((m>>4)*4 + (k0>>4))<<7) + ((ml&7)*4 + ((kl>>1)&3))*4 + r;
        unsigned h,l; split2(v0,v1,h,l); sW2h[w]=h; sW2l[w]=l;
    }
    __syncthreads();

    const int mat=lane>>3, r8=lane&7;
    const int koff=(mat&1)*8 + r8;
    const unsigned bofs = (unsigned)(koff*512 + (((tw3+(mat>>1))^r8)<<4));
    const unsigned xh_s = (unsigned)__cvta_generic_to_shared(sXh);
    const unsigned xl_s = (unsigned)__cvta_generic_to_shared(sXl);

    const int Wout = W-d;
    const int ntiles = (Wout+255)>>8;
    const int sh=d&7, q=sh>>1, odd=sh&1;

    for (int tile=blockIdx.x; tile<ntiles; tile+=gridDim.x){
        const int t0 = tile<<8;
        __syncwarp();
        // stage left rows 0..63, right rows 64..127 (this warp's 16 cols)
        #pragma unroll
        for (int it=0; it<2; it++){
            int c = lane + 32*it;
            size_t g = (size_t)c*HS + t0 + tw;
            int a0 = c*512 + (((tw3)^(c&7))<<4), a1 = c*512 + (((tw3+1)^(c&7))<<4);
            *(uint4*)(sXh+a0) = *(const uint4*)(hinh+g);
            *(uint4*)(sXh+a1) = *(const uint4*)(hinh+g+8);
            *(uint4*)(sXl+a0) = *(const uint4*)(hinl+g);
            *(uint4*)(sXl+a1) = *(const uint4*)(hinl+g+8);
            int k = 64+c;
            int b0a = k*512 + (((tw3)^(c&7))<<4), b1a = k*512 + (((tw3+1)^(c&7))<<4);
            if (sh==0){
                size_t gr = g + d;
                *(uint4*)(sXh+b0a) = *(const uint4*)(hinh+gr);
                *(uint4*)(sXh+b1a) = *(const uint4*)(hinh+gr+8);
                *(uint4*)(sXl+b0a) = *(const uint4*)(hinl+gr);
                *(uint4*)(sXl+b1a) = *(const uint4*)(hinl+gr+8);
            } else {
                size_t gr = g + (d - sh);
                unsigned wh[12], wl[12], oh[8], ol[8];
                *(uint4*)&wh[0]=*(const uint4*)(hinh+gr);   *(uint4*)&wh[4]=*(const uint4*)(hinh+gr+8);
                *(uint4*)&wh[8]=*(const uint4*)(hinh+gr+16);
                *(uint4*)&wl[0]=*(const uint4*)(hinl+gr);   *(uint4*)&wl[4]=*(const uint4*)(hinl+gr+8);
                *(uint4*)&wl[8]=*(const uint4*)(hinl+gr+16);
                #pragma unroll
                for (int i=0;i<8;i++){
                    int s=i+q;
                    oh[i] = odd ? __byte_perm(wh[s],wh[s+1],0x5432) : wh[s];
                    ol[i] = odd ? __byte_perm(wl[s],wl[s+1],0x5432) : wl[s];
                }
                *(uint4*)(sXh+b0a)=*(uint4*)&oh[0]; *(uint4*)(sXh+b1a)=*(uint4*)&oh[4];
                *(uint4*)(sXl+b0a)=*(uint4*)&ol[0]; *(uint4*)(sXl+b1a)=*(uint4*)&ol[4];
            }
        }
        __syncwarp();

        // GEMM1: M=128 N=16 K=128
        float acc[8][2][4];
        #pragma unroll
        for (int a=0;a<8;a++)
            #pragma unroll
            for (int b=0;b<2;b++){ acc[a][b][0]=acc[a][b][1]=acc[a][b][2]=acc[a][b][3]=0.f; }
        #pragma unroll
        for (int kc=0;kc<8;kc++){
            unsigned bh[4], bl[4];
            ldsm4t(xh_s + bofs + kc*8192, bh);
            ldsm4t(xl_s + bofs + kc*8192, bl);
            #pragma unroll
            for (int mt=0;mt<8;mt++){
                uint4 A = *(const uint4*)(sW1h + ((mt*8+kc)<<7) + (lane<<2));
                uint4 B = *(const uint4*)(sW1l + ((mt*8+kc)<<7) + (lane<<2));
                unsigned ah[4]={A.x,A.y,A.z,A.w}, al[4]={B.x,B.y,B.z,B.w};
                mma_bf(acc[mt][0],ah,bh);   mma_bf(acc[mt][1],ah,bh+2);
                mma_bf(acc[mt][0],ah,bl);   mma_bf(acc[mt][1],ah,bl+2);
                mma_bf(acc[mt][0],al,bh);   mma_bf(acc[mt][1],al,bh+2);
            }
        }
        // activations + z -> rows 0..63 of X planes
        #pragma unroll
        for (int mt=0;mt<4;mt++)
            #pragma unroll
            for (int rp=0;rp<2;rp++){
                int mr = mt*16 + (lane>>2) + rp*8;
                float bfv=bfp[mr], bgv=bgp[mr];
                #pragma unroll
                for (int nt=0;nt<2;nt++){
                    float z0 = fast_tanh(acc[mt][nt][rp*2+0]+bfv)*fast_sig(acc[mt+4][nt][rp*2+0]+bgv);
                    float z1 = fast_tanh(acc[mt][nt][rp*2+1]+bfv)*fast_sig(acc[mt+4][nt][rp*2+1]+bgv);
                    unsigned zh,zl; split2(z0,z1,zh,zl);
                    int ad = mr*512 + (((tw3+nt)^(mr&7))<<4) + ((lane&3)<<2);
                    *(unsigned*)(sXh+ad)=zh; *(unsigned*)(sXl+ad)=zl;
                }
            }
        __syncwarp();

        // GEMM2: M=128 N=16 K=64
        float ac2[8][2][4];
        #pragma unroll
        for (int a=0;a<8;a++)
            #pragma unroll
            for (int b=0;b<2;b++){ ac2[a][b][0]=ac2[a][b][1]=ac2[a][b][2]=ac2[a][b][3]=0.f; }
        #pragma unroll
        for (int kc=0;kc<4;kc++){
            unsigned bh[4], bl[4];
            ldsm4t(xh_s + bofs + kc*8192, bh);
            ldsm4t(xl_s + bofs + kc*8192, bl);
            #pragma unroll
            for (int mt=0;mt<8;mt++){
                uint4 A = *(const uint4*)(sW2h + ((mt*4+kc)<<7) + (lane<<2));
                uint4 B = *(const uint4*)(sW2l + ((mt*4+kc)<<7) + (lane<<2));
                unsigned ah[4]={A.x,A.y,A.z,A.w}, al[4]={B.x,B.y,B.z,B.w};
                mma_bf(ac2[mt][0],ah,bh);   mma_bf(ac2[mt][1],ah,bh+2);
                mma_bf(ac2[mt][0],ah,bl);   mma_bf(ac2[mt][1],ah,bl+2);
                mma_bf(ac2[mt][0],al,bh);   mma_bf(ac2[mt][1],al,bh+2);
            }
        }

        const bool full = (t0+256 <= Wout);
        #pragma unroll
        for (int mt=0;mt<4;mt++)
            #pragma unroll
            for (int rp=0;rp<2;rp++){
                int mr = mt*16 + (lane>>2) + rp*8;
                float bias = brp[mr];
                #pragma unroll
                for (int nt=0;nt<2;nt++){
                    int gt = t0 + tw + nt*8 + ((lane&3)<<1);
                    int ra = (64+mr)*512 + (((tw3+nt)^(mr&7))<<4) + ((lane&3)<<2);
                    unsigned rh=*(unsigned*)(sXh+ra), rl=*(unsigned*)(sXl+ra);
                    float v0 = ac2[mt][nt][rp*2+0] + bias + blo(rh) + blo(rl);
                    float v1 = ac2[mt][nt][rp*2+1] + bias + bhi(rh) + bhi(rl);
                    size_t go = (size_t)mr*HS + gt;
                    if (full){
                        unsigned oh,ol; split2(v0,v1,oh,ol);
                        *(unsigned*)(houth+go)=oh; *(unsigned*)(houtl+go)=ol;
                    } else {
                        if (gt < Wout){ __nv_bfloat16 h=__float2bfloat16(v0);
                            houth[go]=h; houtl[go]=__float2bfloat16(v0-__bfloat162float(h)); }
                        if (gt+1 < Wout){ __nv_bfloat16 h=__float2bfloat16(v1);
                            houth[go+1]=h; houtl[go+1]=__float2bfloat16(v1-__bfloat162float(h)); }
                    }
                }
            }
        #pragma unroll
        for (int mt=4;mt<8;mt++)
            #pragma unroll
            for (int rp=0;rp<2;rp++){
                int sr = (mt-4)*16 + (lane>>2) + rp*8;
                float bias = bsp[sr];
                #pragma unroll
                for (int nt=0;nt<2;nt++){
                    int gt = t0 + tw + nt*8 + ((lane&3)<<1);
                    #pragma unroll
                    for (int e=0;e<2;e++){
                        int gc = gt+e - skip_shift;
                        if (gt+e < Wout && gc >= 0 && gc < TOUT){
                            float* p = &g_skip[sr*TOUT+gc];
                            *p = *p + ac2[mt][nt][rp*2+e] + bias;
                        }
                    }
                }
            }
    }
}

// -------- output head (R2 machinery, known correct) --------
__device__ __forceinline__ unsigned pack_hl(float x){
    __nv_bfloat16 h=__float2bfloat16(x);
    __nv_bfloat16 l=__float2bfloat16(x-__bfloat162float(h));
    return (unsigned)__bfloat16_as_ushort(h) | ((unsigned)__bfloat16_as_ushort(l)<<16);
}
__device__ __forceinline__ int addrA(int m,int k,int kt){
    int ln=((m&7)<<2)|((k>>1)&3);
    int w=(k&1)|(((m>>3)&1)<<1)|(((k>>3)&1)<<2);
    return ((((m>>4)*kt+(k>>4))<<8)+(ln<<3)+w);
}
__device__ __forceinline__ int addrB(int k,int t){
    int ln=((t&7)<<2)|((k>>1)&3);
    int w=(k&1)|(((k>>3)&1)<<1);
    return ((((k>>4)*(FTT>>3)+(t>>3))<<7)+(ln<<2)+w);
}
__device__ __forceinline__ void loadA(const unsigned* s,int mt,int kc,int kt,int lane,unsigned* Ah,unsigned* Al){
    const uint4* p=(const uint4*)(s+(((mt*kt+kc)<<8)+(lane<<3)));
    uint4 q0=p[0],q1=p[1];
    Ah[0]=__byte_perm(q0.x,q0.y,0x5410); Al[0]=__byte_perm(q0.x,q0.y,0x7632);
    Ah[1]=__byte_perm(q0.z,q0.w,0x5410); Al[1]=__byte_perm(q0.z,q0.w,0x7632);
    Ah[2]=__byte_perm(q1.x,q1.y,0x5410); Al[2]=__byte_perm(q1.x,q1.y,0x7632);
    Ah[3]=__byte_perm(q1.z,q1.w,0x5410); Al[3]=__byte_perm(q1.z,q1.w,0x7632);
}
__device__ __forceinline__ void loadB(const unsigned* s,int kc,int nt,int lane,unsigned* Bh,unsigned* Bl){
    uint4 q=*(const uint4*)(s+(((kc*(FTT>>3)+nt)<<7)+(lane<<2)));
    Bh[0]=__byte_perm(q.x,q.y,0x5410); Bl[0]=__byte_perm(q.x,q.y,0x7632);
    Bh[1]=__byte_perm(q.z,q.w,0x5410); Bl[1]=__byte_perm(q.z,q.w,0x7632);
}

__global__ void __launch_bounds__(512,1) final_kernel(
    const float* __restrict__ alpha,
    const float* __restrict__ w0p, const float* __restrict__ b0p,
    const float* __restrict__ w1p, const float* __restrict__ b1p,
    float* __restrict__ out)
{
    extern __shared__ unsigned fs[];
    unsigned* sW0=fs; unsigned* sW1=fs+4096; unsigned* sB0=fs+20480; unsigned* sB1=fs+28672;
    const int tid=threadIdx.x, lane=tid&31, wrp=tid>>5;
    const int wm=wrp>>2, n0=(wrp&3)*32;

    for (int i=tid;i<64*64;i+=512) sW0[addrA(i>>6,i&63,4)]=pack_hl(w0p[i]);
    for (int i=tid;i<256*64;i+=512) sW1[addrA(i>>6,i&63,4)]=pack_hl(w1p[i]);
    __syncthreads();

    const int nt_total=(TOUT+FTT-1)/FTT;
    for (int tile=blockIdx.x; tile<nt_total; tile+=gridDim.x){
        const int t0=tile*FTT;
        for (int i=tid;i<64*FTT;i+=512){
            int c=i>>7, t=i&(FTT-1), gt=t0+t;
            float v=(gt<TOUT)?g_skip[c*TOUT+gt]:0.0f;
            v=(v>0.f)?v:alpha[c]*v;
            sB0[addrB(c,t)]=pack_hl(v);
        }
        __syncthreads();

        float a0[4][4];
        #pragma unroll
        for (int b=0;b<4;b++){ a0[b][0]=a0[b][1]=a0[b][2]=a0[b][3]=0.f; }
        #pragma unroll
        for (int kc=0;kc<4;kc++){
            unsigned Ah[4],Al[4],Bh[4][2],Bl[4][2];
            loadA(sW0,wm,kc,4,lane,Ah,Al);
            #pragma unroll
            for (int nt=0;nt<4;nt++) loadB(sB0,kc,(n0>>3)+nt,lane,Bh[nt],Bl[nt]);
            #pragma unroll
            for (int nt=0;nt<4;nt++){
                mma_bf(a0[nt],Ah,Bh[nt]); mma_bf(a0[nt],Ah,Bl[nt]); mma_bf(a0[nt],Al,Bh[nt]);
            }
        }
        #pragma unroll
        for (int nt=0;nt<4;nt++){
            int tb=n0+nt*8+((lane&3)<<1);
            #pragma unroll
            for (int r=0;r<4;r++){
                int m=wm*16+(lane>>2)+((r&2)?8:0);
                float v=a0[nt][r]+b0p[m];
                v=(v>0.f)?v:alpha[64+m]*v;
                sB1[addrB(m,tb+(r&1))]=pack_hl(v);
            }
        }
        __syncthreads();

        float a1[4][4][4];
        #pragma unroll
        for (int a=0;a<4;a++)
            #pragma unroll
            for (int b=0;b<4;b++){ a1[a][b][0]=a1[a][b][1]=a1[a][b][2]=a1[a][b][3]=0.f; }
        #pragma unroll
        for (int kc=0;kc<4;kc++){
            unsigned Ah[4][4],Al[4][4],Bh[4][2],Bl[4][2];
            #pragma unroll
            for (int mt=0;mt<4;mt++) loadA(sW1,wm*4+mt,kc,4,lane,Ah[mt],Al[mt]);
            #pragma unroll
            for (int nt=0;nt<4;nt++) loadB(sB1,kc,(n0>>3)+nt,lane,Bh[nt],Bl[nt]);
            #pragma unroll
            for (int mt=0;mt<4;mt++)
                #pragma unroll
                for (int nt=0;nt<4;nt++){
                    mma_bf(a1[mt][nt],Ah[mt],Bh[nt]); mma_bf(a1[mt][nt],Ah[mt],Bl[nt]); mma_bf(a1[mt][nt],Al[mt],Bh[nt]);
                }
        }
        #pragma unroll
        for (int mt=0;mt<4;mt++){
            int mb=wm*64+mt*16+(lane>>2);
            #pragma unroll
            for (int nt=0;nt<4;nt++){
                int tb=n0+nt*8+((lane&3)<<1);
                #pragma unroll
                for (int r=0;r<4;r++){
                    int m=mb+((r&2)?8:0), gt=t0+tb+(r&1);
                    if (gt<TOUT) out[m*TOUT+gt]=a1[mt][nt][r]+b1p[m];
                }
            }
        }
        __syncthreads();
    }
}

extern "C" void kernel_launch(void* const* d_in, const int* in_sizes, int n_in,
                              void* d_out, int out_size) {
    const float* input =(const float*)d_in[0];
    const float* w0    =(const float*)d_in[1];
    const float* b0    =(const float*)d_in[2];
    const float* wf    =(const float*)d_in[3];
    const float* bf    =(const float*)d_in[4];
    const float* wg    =(const float*)d_in[5];
    const float* bg    =(const float*)d_in[6];
    const float* wr    =(const float*)d_in[7];
    const float* br    =(const float*)d_in[8];
    const float* ws    =(const float*)d_in[9];
    const float* bs    =(const float*)d_in[10];
    const float* alpha =(const float*)d_in[11];
    const float* w_out0=(const float*)d_in[12];
    const float* b_out0=(const float*)d_in[13];
    const float* w_out1=(const float*)d_in[14];
    const float* b_out1=(const float*)d_in[15];

    const int SMEM_LAYER = 229376;
    const int SMEM_FINAL = 36864*4;
    cudaFuncSetAttribute(layer_kernel, cudaFuncAttributeMaxDynamicSharedMemorySize, SMEM_LAYER);
    cudaFuncSetAttribute(final_kernel, cudaFuncAttributeMaxDynamicSharedMemorySize, SMEM_FINAL);

    init_kernel<<<512,256>>>(input, w0, b0);

    int W = HS, offset = 2048, buf = 0;
    for (int i = 0; i < NLAYER; i++){
        int d = 1 << (i % 10);
        offset -= d;
        layer_kernel<<<148,512,SMEM_LAYER>>>(
            wf + i*64*64*2, wg + i*64*64*2, wr + i*64*64, ws + i*64*64,
            bf + i*64, bg + i*64, br + i*64, bs + i*64,
            buf, W, d, offset - 1);
        W -= d; buf ^= 1;
    }
    final_kernel<<<148,512,SMEM_FINAL>>>(alpha, w_out0, b_out0, w_out1, b_out1, (float*)d_out);
}